// round 9
// baseline (speedup 1.0000x reference)
#include <cuda_runtime.h>

#define BATCH 256
#define VOCAB 128000
#define RANK  64
#define ALPHA 0.4f
#define EPSF  1.1920928955078125e-07f   // np.finfo(float32).eps

#define KC   160                 // k-chunk per gemm1 block
#define NKC  (VOCAB / KC)        // 800 k-chunks
#define BH   128                 // batch-half per gemm1 block
#define PART_SZ (BH * RANK)      // 8192 floats per partial

// ---------------- scratch (no allocations allowed) ----------------
__device__ float        g_Tpart[2 * NKC * PART_SZ];  // per-block partial T (52 MB)
__device__ float        g_T[BATCH * RANK];           // reduced T = L @ W
__device__ unsigned int g_maxL;                      // float bits of max|L|
__device__ unsigned int g_maxLp;                     // float bits of max|Lp_raw|

// ---------------- f32x2 / shared-memory PTX helpers ----------------
typedef unsigned long long u64;

__device__ __forceinline__ unsigned smem_u32(const void* p) {
    unsigned a;
    asm("{ .reg .u64 t; cvta.to.shared.u64 t, %1; cvt.u32.u64 %0, t; }"
        : "=r"(a) : "l"(p));
    return a;
}
__device__ __forceinline__ u64 lds_b64(unsigned a) {
    u64 v; asm volatile("ld.shared.b64 %0, [%1];" : "=l"(v) : "r"(a)); return v;
}
__device__ __forceinline__ float lds_b32(unsigned a) {
    float v; asm volatile("ld.shared.b32 %0, [%1];" : "=f"(v) : "r"(a)); return v;
}
__device__ __forceinline__ void sts_b32(unsigned a, float v) {
    asm volatile("st.shared.b32 [%0], %1;" :: "r"(a), "f"(v));
}
__device__ __forceinline__ void sts_b64(unsigned a, u64 v) {
    asm volatile("st.shared.b64 [%0], %1;" :: "r"(a), "l"(v));
}
__device__ __forceinline__ u64 fma2(u64 a, u64 b, u64 c) {
    u64 d; asm("fma.rn.f32x2 %0, %1, %2, %3;" : "=l"(d) : "l"(a), "l"(b), "l"(c));
    return d;
}
__device__ __forceinline__ u64 pack2(float x, float y) {
    u64 v; asm("mov.b64 %0, {%1,%2};" : "=l"(v) : "f"(x), "f"(y)); return v;
}
__device__ __forceinline__ void unpack2(u64 v, float& x, float& y) {
    asm("mov.b64 {%0,%1}, %2;" : "=f"(x), "=f"(y) : "l"(v));
}

// ---------------- K0: init g_T + maxima ----------------
__global__ void k_init() {
    int i = blockIdx.x * blockDim.x + threadIdx.x;
    if (i < BATCH * RANK) g_T[i] = 0.0f;
    if (i == 0) { g_maxL = 0u; g_maxLp = 0u; }
}

// ---------------- K1: partial T = L@W (rank-paired FFMA2, fused max|L|) ----------------
// grid = (NKC, 2 batch-halves), 256 threads. Block tile: 128 b x 64 r x KC.
// Thread tile: 4 b x 8 r (4 native rank-pairs, r = tx*2 + jp*16).
#define KB 32
#define LS1 33                  // Ls[b][kk] stride (scalar ops, conflict-free)
#define WS1 66                  // Ws[kk][r] stride (even -> b64-aligned pairs)
#define G1_SMEM ((BH * LS1 + KB * WS1) * 4)      // 16896 + 8448 B = 25344 B

__global__ __launch_bounds__(256, 4) void k_gemm1(const float* __restrict__ L,
                                                  const float* __restrict__ W) {
    extern __shared__ float sm1[];
    float* Ls = sm1;                      // [128][33]
    float* Ws = sm1 + BH * LS1;           // [32][66]
    __shared__ float wred[8];

    const unsigned ls_base = smem_u32(Ls);
    const unsigned ws_base = smem_u32(Ws);

    const int tid = threadIdx.x;
    const int tx  = tid & 7;    // rank-pair lane
    const int ty  = tid >> 3;   // batch group (4 rows each)
    const int k0blk = blockIdx.x * KC;
    const int bbase = blockIdx.y * BH;

    u64 acc[4][4];
#pragma unroll
    for (int i = 0; i < 4; i++)
#pragma unroll
        for (int jp = 0; jp < 4; jp++) acc[i][jp] = 0ull;

    float maxl = 0.0f;

    for (int kt = 0; kt < KC; kt += KB) {
        const int k0 = k0blk + kt;
        __syncthreads();
        // L chunk [128 b][32 k] -> Ls[b][kk]; fused abs-max
#pragma unroll
        for (int it = 0; it < 4; it++) {
            int idx = tid + it * 256;          // float4 index, 1024 total
            int b   = idx >> 3;
            int kq  = idx & 7;
            float4 v = *(const float4*)(L + (size_t)(bbase + b) * VOCAB + k0 + kq * 4);
            maxl = fmaxf(maxl, fmaxf(fmaxf(fabsf(v.x), fabsf(v.y)),
                                     fmaxf(fabsf(v.z), fabsf(v.w))));
            unsigned a = ls_base + (b * LS1 + kq * 4) * 4;
            sts_b32(a +  0, v.x);
            sts_b32(a +  4, v.y);
            sts_b32(a +  8, v.z);
            sts_b32(a + 12, v.w);
        }
        // W chunk [32 k][64 r] -> Ws[kk][r] (b64 stores)
#pragma unroll
        for (int it = 0; it < 2; it++) {
            int idx = tid + it * 256;          // float4 index, 512 total
            int kk  = idx >> 4;
            int rq  = idx & 15;
            float4 v = *(const float4*)(W + (size_t)(k0 + kk) * RANK + rq * 4);
            unsigned a = ws_base + (kk * WS1 + rq * 4) * 4;
            sts_b64(a + 0, pack2(v.x, v.y));
            sts_b64(a + 8, pack2(v.z, v.w));
        }
        __syncthreads();

#pragma unroll
        for (int kk = 0; kk < KB; kk++) {
            // native W rank-pairs: r = tx*2 + jp*16
            const unsigned wa = ws_base + (kk * WS1 + tx * 2) * 4;
            u64 wp[4];
#pragma unroll
            for (int jp = 0; jp < 4; jp++) wp[jp] = lds_b64(wa + jp * 64);
            // L scalars, register-duplicated
            const unsigned la = ls_base + (ty * 4 * LS1 + kk) * 4;
#pragma unroll
            for (int i = 0; i < 4; i++) {
                float lv = lds_b32(la + i * LS1 * 4);
                u64 lp = pack2(lv, lv);
#pragma unroll
                for (int jp = 0; jp < 4; jp++)
                    acc[i][jp] = fma2(lp, wp[jp], acc[i][jp]);
            }
        }
    }

    // write per-block partial tile (no atomics): partial index = half*NKC + kc
    {
        float* dst = g_Tpart +
            (size_t)(blockIdx.y * NKC + blockIdx.x) * PART_SZ;
#pragma unroll
        for (int i = 0; i < 4; i++) {
            int b = ty * 4 + i;
#pragma unroll
            for (int jp = 0; jp < 4; jp++)
                *(u64*)(dst + b * RANK + tx * 2 + jp * 16) = acc[i][jp];
        }
    }

    // block-reduce max|L|
#pragma unroll
    for (int off = 16; off > 0; off >>= 1)
        maxl = fmaxf(maxl, __shfl_xor_sync(0xffffffffu, maxl, off));
    __syncthreads();
    if ((tid & 31) == 0) wred[tid >> 5] = maxl;
    __syncthreads();
    if (tid == 0) {
        float m = wred[0];
#pragma unroll
        for (int k = 1; k < 8; k++) m = fmaxf(m, wred[k]);
        atomicMax(&g_maxL, __float_as_uint(m));
    }
}

// ---------------- K1b: reduce partials -> g_T ----------------
// grid = (BATCH*RANK/256, 8 kc-groups). Each block sums NKC/8 partials, atomicAdd.
#define KGRP 8
#define KPER (NKC / KGRP)       // 100
__global__ void k_red() {
    const int i = blockIdx.x * blockDim.x + threadIdx.x;   // (b,r) flat
    const int b = i >> 6;
    const int r = i & 63;
    const int half = b >> 7;
    const size_t off = (size_t)(b & 127) * RANK + r;
    const size_t base = ((size_t)half * NKC + blockIdx.y * KPER) * PART_SZ + off;

    float s0 = 0.f, s1 = 0.f, s2 = 0.f, s3 = 0.f;
#pragma unroll 4
    for (int p = 0; p < KPER; p += 4) {
        s0 += g_Tpart[base + (size_t)(p + 0) * PART_SZ];
        s1 += g_Tpart[base + (size_t)(p + 1) * PART_SZ];
        s2 += g_Tpart[base + (size_t)(p + 2) * PART_SZ];
        s3 += g_Tpart[base + (size_t)(p + 3) * PART_SZ];
    }
    atomicAdd(&g_T[i], (s0 + s1) + (s2 + s3));
}

// ---------------- K2: Lp = T@W.T - L (batch-paired FFMA2) ----------------
// grid = (VOCAB/64, 2), 256 threads. Block tile 128 b x 64 j.
// Thread: 8 b (4 native b-pairs from Tt) x 4 j (j = tx + jj*16). Scalar W -> reg dup.
#define JB 64
#define BT 128
#define TT2 130                 // Tt[r][b] stride (even -> b64 pairs aligned)
#define WS2 65                  // Ws[j][r] stride (scalar loads, conflict-free)
#define SMEM2_BYTES ((RANK * TT2 + JB * WS2) * 4)   // 33280 + 16640 B = 49920 B

__global__ __launch_bounds__(256, 4) void k_gemm2(const float* __restrict__ L,
                                                  const float* __restrict__ W,
                                                  float* __restrict__ out) {
    extern __shared__ float sm[];
    float* Tt = sm;                  // [64 r][130]
    float* Ws = sm + RANK * TT2;     // [64 j][65]

    const unsigned tt_base = smem_u32(Tt);
    const unsigned ws_base = smem_u32(Ws);

    const int tid = threadIdx.x;
    const int tx  = tid & 15;       // j lane
    const int ty  = tid >> 4;       // b group (8 rows = 4 pairs)
    const int j0  = blockIdx.x * JB;
    const int b0  = blockIdx.y * BT;

    // load T slice [128 b][64 r] transposed -> Tt[r][b]
#pragma unroll
    for (int it = 0; it < 8; it++) {
        int idx = tid + it * 256;        // float4 index, 2048 total
        int b   = idx >> 4;
        int rq  = idx & 15;
        float4 v = *(const float4*)(g_T + (size_t)(b0 + b) * RANK + rq * 4);
        unsigned a = tt_base + (rq * 4 * TT2 + b) * 4;
        sts_b32(a + 0 * TT2 * 4, v.x);
        sts_b32(a + 1 * TT2 * 4, v.y);
        sts_b32(a + 2 * TT2 * 4, v.z);
        sts_b32(a + 3 * TT2 * 4, v.w);
    }
    // load W tile [64 j][64 r] -> Ws[j][r]
#pragma unroll
    for (int it = 0; it < 4; it++) {
        int idx = tid + it * 256;        // 1024 float4
        int jj  = idx >> 4;
        int rq  = idx & 15;
        float4 v = *(const float4*)(W + (size_t)(j0 + jj) * RANK + rq * 4);
        unsigned a = ws_base + (jj * WS2 + rq * 4) * 4;
        sts_b32(a +  0, v.x);
        sts_b32(a +  4, v.y);
        sts_b32(a +  8, v.z);
        sts_b32(a + 12, v.w);
    }
    __syncthreads();

    u64 acc[4][4];                  // [b-pair][j]
#pragma unroll
    for (int ip = 0; ip < 4; ip++)
#pragma unroll
        for (int j = 0; j < 4; j++) acc[ip][j] = 0ull;

#pragma unroll 8
    for (int r = 0; r < RANK; r++) {
        // native T b-pairs: b = ty*8 + ip*2
        const unsigned ta = tt_base + (r * TT2 + ty * 8) * 4;
        u64 tp[4];
#pragma unroll
        for (int ip = 0; ip < 4; ip++) tp[ip] = lds_b64(ta + ip * 8);
        // W scalars, register-duplicated: j = tx + jj*16
        const unsigned wa = ws_base + (tx * WS2 + r) * 4;
#pragma unroll
        for (int jj = 0; jj < 4; jj++) {
            float wv = lds_b32(wa + jj * 16 * WS2 * 4);
            u64 wp = pack2(wv, wv);
#pragma unroll
            for (int ip = 0; ip < 4; ip++)
                acc[ip][jj] = fma2(tp[ip], wp, acc[ip][jj]);
        }
    }

    // epilogue: Lp = acc - L, write raw Lp, track max|Lp|
    float maxlp = 0.0f;
#pragma unroll
    for (int ip = 0; ip < 4; ip++) {
        const size_t bA = (size_t)(b0 + ty * 8 + ip * 2);
        const size_t bB = bA + 1;
#pragma unroll
        for (int jj = 0; jj < 4; jj++) {
            float lo, hi;
            unpack2(acc[ip][jj], lo, hi);
            int j = j0 + tx + jj * 16;
            float oa = lo - L[bA * VOCAB + j];
            float ob = hi - L[bB * VOCAB + j];
            maxlp = fmaxf(maxlp, fmaxf(fabsf(oa), fabsf(ob)));
            out[bA * VOCAB + j] = oa;
            out[bB * VOCAB + j] = ob;
        }
    }

#pragma unroll
    for (int off = 16; off > 0; off >>= 1)
        maxlp = fmaxf(maxlp, __shfl_xor_sync(0xffffffffu, maxlp, off));
    __syncthreads();                 // smem reads done -> reuse for reduction
    if ((tid & 31) == 0) Tt[tid >> 5] = maxlp;
    __syncthreads();
    if (tid == 0) {
        float m = Tt[0];
#pragma unroll
        for (int k = 1; k < 8; k++) m = fmaxf(m, Tt[k]);
        atomicMax(&g_maxLp, __float_as_uint(m));
    }
}

// ---------------- K3: out = (1-a)*scale*Lp + a*L ----------------
__global__ void k_final(const float* __restrict__ L, float* __restrict__ out) {
    const float maxl  = __uint_as_float(g_maxL);
    const float maxlp = __uint_as_float(g_maxLp);
    const float scale = maxl / fmaxf(maxlp, EPSF);
    const float c2 = (1.0f - ALPHA) * scale;

    const int n4 = BATCH * VOCAB / 4;
    float4* o4 = (float4*)out;
    const float4* l4 = (const float4*)L;
    for (int i = blockIdx.x * blockDim.x + threadIdx.x; i < n4;
         i += gridDim.x * blockDim.x) {
        float4 o = o4[i];
        float4 l = l4[i];
        o.x = fmaf(c2, o.x, ALPHA * l.x);
        o.y = fmaf(c2, o.y, ALPHA * l.y);
        o.z = fmaf(c2, o.z, ALPHA * l.z);
        o.w = fmaf(c2, o.w, ALPHA * l.w);
        o4[i] = o;
    }
}

// ---------------- launch ----------------
extern "C" void kernel_launch(void* const* d_in, const int* in_sizes, int n_in,
                              void* d_out, int out_size) {
    const float* L = nullptr;
    const float* W = nullptr;
    for (int i = 0; i < n_in; i++) {
        if (in_sizes[i] == BATCH * VOCAB)     L = (const float*)d_in[i];
        else if (in_sizes[i] == VOCAB * RANK) W = (const float*)d_in[i];
    }
    if (!L && n_in >= 2) L = (const float*)d_in[1];
    if (!W && n_in >= 3) W = (const float*)d_in[2];
    float* out = (float*)d_out;

    cudaFuncSetAttribute(k_gemm1, cudaFuncAttributeMaxDynamicSharedMemorySize,
                         G1_SMEM);
    cudaFuncSetAttribute(k_gemm2, cudaFuncAttributeMaxDynamicSharedMemorySize,
                         SMEM2_BYTES);

    k_init<<<(BATCH * RANK) / 256, 256>>>();
    k_gemm1<<<dim3(NKC, 2), 256, G1_SMEM>>>(L, W);
    k_red<<<dim3((BATCH * RANK) / 256, KGRP), 256>>>();
    k_gemm2<<<dim3(VOCAB / JB, BATCH / BT), 256, SMEM2_BYTES>>>(L, W, out);
    k_final<<<4000, 256>>>(L, out);
}

// round 11
// speedup vs baseline: 1.1812x; 1.1812x over previous
#include <cuda_runtime.h>
#include <cstdint>

#define BATCH 256
#define VOCAB 128000
#define RANK  64
#define ALPHA 0.4f
#define EPSF  1.1920928955078125e-07f   // np.finfo(float32).eps

#define KC   160                 // k-chunk per gemm1 block
#define NKC  (VOCAB / KC)        // 800 k-chunks
#define BH   128                 // batch-half per gemm1 block
#define PART_SZ (BH * RANK)      // 8192 floats per partial

// ---------------- scratch (no allocations allowed) ----------------
__device__ float        g_Tpart[2 * NKC * PART_SZ];  // per-block partial T (52 MB)
__device__ float        g_T[BATCH * RANK];           // reduced T = L @ W
__device__ unsigned int g_maxL;                      // float bits of max|L|
__device__ unsigned int g_maxLp;                     // float bits of max|Lp_raw|

// ---------------- PTX helpers ----------------
typedef unsigned long long u64;

__device__ __forceinline__ unsigned smem_u32(const void* p) {
    unsigned a;
    asm("{ .reg .u64 t; cvta.to.shared.u64 t, %1; cvt.u32.u64 %0, t; }"
        : "=r"(a) : "l"(p));
    return a;
}
__device__ __forceinline__ u64 lds_b64(unsigned a) {
    u64 v; asm volatile("ld.shared.b64 %0, [%1];" : "=l"(v) : "r"(a)); return v;
}
__device__ __forceinline__ float lds_b32f(unsigned a) {
    float v; asm volatile("ld.shared.b32 %0, [%1];" : "=f"(v) : "r"(a)); return v;
}
__device__ __forceinline__ void sts_b32(unsigned a, float v) {
    asm volatile("st.shared.b32 [%0], %1;" :: "r"(a), "f"(v));
}
__device__ __forceinline__ void sts_b64(unsigned a, u64 v) {
    asm volatile("st.shared.b64 [%0], %1;" :: "r"(a), "l"(v));
}
__device__ __forceinline__ u64 fma2(u64 a, u64 b, u64 c) {
    u64 d; asm("fma.rn.f32x2 %0, %1, %2, %3;" : "=l"(d) : "l"(a), "l"(b), "l"(c));
    return d;
}
__device__ __forceinline__ u64 pack2(float x, float y) {
    u64 v; asm("mov.b64 %0, {%1,%2};" : "=l"(v) : "f"(x), "f"(y)); return v;
}

// ldmatrix (sm_75+, valid on compute_103)
__device__ __forceinline__ void ldm_x4(unsigned addr, unsigned* r) {
    asm volatile("ldmatrix.sync.aligned.m8n8.x4.shared.b16 {%0,%1,%2,%3}, [%4];"
                 : "=r"(r[0]), "=r"(r[1]), "=r"(r[2]), "=r"(r[3]) : "r"(addr));
}
__device__ __forceinline__ void ldm_x2(unsigned addr, unsigned* r) {
    asm volatile("ldmatrix.sync.aligned.m8n8.x2.shared.b16 {%0,%1}, [%2];"
                 : "=r"(r[0]), "=r"(r[1]) : "r"(addr));
}
// bf16 mma (sm_80+, valid on compute_103)
__device__ __forceinline__ void mma_bf16(float* c, const unsigned* a, const unsigned* b) {
    asm volatile(
        "mma.sync.aligned.m16n8k16.row.col.f32.bf16.bf16.f32 "
        "{%0,%1,%2,%3}, {%4,%5,%6,%7}, {%8,%9}, {%0,%1,%2,%3};"
        : "+f"(c[0]), "+f"(c[1]), "+f"(c[2]), "+f"(c[3])
        : "r"(a[0]), "r"(a[1]), "r"(a[2]), "r"(a[3]), "r"(b[0]), "r"(b[1]));
}

// fp32 -> (hi,lo) bf16 split of a float4; each u64 = 4 packed bf16 in element order
__device__ __forceinline__ void split4(float4 v, u64& hi, u64& lo) {
    unsigned h01, h23, l01, l23;
    asm("cvt.rn.bf16x2.f32 %0, %1, %2;" : "=r"(h01) : "f"(v.y), "f"(v.x));
    asm("cvt.rn.bf16x2.f32 %0, %1, %2;" : "=r"(h23) : "f"(v.w), "f"(v.z));
    float hx = __uint_as_float(h01 << 16);
    float hy = __uint_as_float(h01 & 0xffff0000u);
    float hz = __uint_as_float(h23 << 16);
    float hw = __uint_as_float(h23 & 0xffff0000u);
    asm("cvt.rn.bf16x2.f32 %0, %1, %2;" : "=r"(l01) : "f"(v.y - hy), "f"(v.x - hx));
    asm("cvt.rn.bf16x2.f32 %0, %1, %2;" : "=r"(l23) : "f"(v.w - hw), "f"(v.z - hz));
    hi = (u64)h01 | ((u64)h23 << 32);
    lo = (u64)l01 | ((u64)l23 << 32);
}

// ---------------- K0: init g_T + maxima ----------------
__global__ void k_init() {
    int i = blockIdx.x * blockDim.x + threadIdx.x;
    if (i < BATCH * RANK) g_T[i] = 0.0f;
    if (i == 0) { g_maxL = 0u; g_maxLp = 0u; }
}

// ---------------- K1: partial T = L@W (rank-paired FFMA2, fused max|L|) ----------------
#define KB 32
#define LS1 33
#define WS1 66
#define G1_SMEM ((BH * LS1 + KB * WS1) * 4)      // 25344 B

__global__ __launch_bounds__(256, 4) void k_gemm1(const float* __restrict__ L,
                                                  const float* __restrict__ W) {
    extern __shared__ float sm1[];
    float* Ls = sm1;                      // [128][33]
    float* Ws = sm1 + BH * LS1;           // [32][66]
    __shared__ float wred[8];

    const unsigned ls_base = smem_u32(Ls);
    const unsigned ws_base = smem_u32(Ws);

    const int tid = threadIdx.x;
    const int tx  = tid & 7;
    const int ty  = tid >> 3;
    const int k0blk = blockIdx.x * KC;
    const int bbase = blockIdx.y * BH;

    u64 acc[4][4];
#pragma unroll
    for (int i = 0; i < 4; i++)
#pragma unroll
        for (int jp = 0; jp < 4; jp++) acc[i][jp] = 0ull;

    float maxl = 0.0f;

    for (int kt = 0; kt < KC; kt += KB) {
        const int k0 = k0blk + kt;
        __syncthreads();
#pragma unroll
        for (int it = 0; it < 4; it++) {
            int idx = tid + it * 256;
            int b   = idx >> 3;
            int kq  = idx & 7;
            float4 v = *(const float4*)(L + (size_t)(bbase + b) * VOCAB + k0 + kq * 4);
            maxl = fmaxf(maxl, fmaxf(fmaxf(fabsf(v.x), fabsf(v.y)),
                                     fmaxf(fabsf(v.z), fabsf(v.w))));
            unsigned a = ls_base + (b * LS1 + kq * 4) * 4;
            sts_b32(a +  0, v.x);
            sts_b32(a +  4, v.y);
            sts_b32(a +  8, v.z);
            sts_b32(a + 12, v.w);
        }
#pragma unroll
        for (int it = 0; it < 2; it++) {
            int idx = tid + it * 256;
            int kk  = idx >> 4;
            int rq  = idx & 15;
            float4 v = *(const float4*)(W + (size_t)(k0 + kk) * RANK + rq * 4);
            unsigned a = ws_base + (kk * WS1 + rq * 4) * 4;
            sts_b64(a + 0, pack2(v.x, v.y));
            sts_b64(a + 8, pack2(v.z, v.w));
        }
        __syncthreads();

#pragma unroll
        for (int kk = 0; kk < KB; kk++) {
            const unsigned wa = ws_base + (kk * WS1 + tx * 2) * 4;
            u64 wp[4];
#pragma unroll
            for (int jp = 0; jp < 4; jp++) wp[jp] = lds_b64(wa + jp * 64);
            const unsigned la = ls_base + (ty * 4 * LS1 + kk) * 4;
#pragma unroll
            for (int i = 0; i < 4; i++) {
                float lv = lds_b32f(la + i * LS1 * 4);
                u64 lp = pack2(lv, lv);
#pragma unroll
                for (int jp = 0; jp < 4; jp++)
                    acc[i][jp] = fma2(lp, wp[jp], acc[i][jp]);
            }
        }
    }

    {
        float* dst = g_Tpart + (size_t)(blockIdx.y * NKC + blockIdx.x) * PART_SZ;
#pragma unroll
        for (int i = 0; i < 4; i++) {
            int b = ty * 4 + i;
#pragma unroll
            for (int jp = 0; jp < 4; jp++)
                *(u64*)(dst + b * RANK + tx * 2 + jp * 16) = acc[i][jp];
        }
    }

#pragma unroll
    for (int off = 16; off > 0; off >>= 1)
        maxl = fmaxf(maxl, __shfl_xor_sync(0xffffffffu, maxl, off));
    __syncthreads();
    if ((tid & 31) == 0) wred[tid >> 5] = maxl;
    __syncthreads();
    if (tid == 0) {
        float m = wred[0];
#pragma unroll
        for (int k = 1; k < 8; k++) m = fmaxf(m, wred[k]);
        atomicMax(&g_maxL, __float_as_uint(m));
    }
}

// ---------------- K1b: reduce partials -> g_T ----------------
#define KGRP 8
#define KPER (NKC / KGRP)       // 100
__global__ void k_red() {
    const int i = blockIdx.x * blockDim.x + threadIdx.x;
    const int b = i >> 6;
    const int r = i & 63;
    const int half = b >> 7;
    const size_t off = (size_t)(b & 127) * RANK + r;
    const size_t base = ((size_t)half * NKC + blockIdx.y * KPER) * PART_SZ + off;

    float s0 = 0.f, s1 = 0.f, s2 = 0.f, s3 = 0.f;
#pragma unroll 4
    for (int p = 0; p < KPER; p += 4) {
        s0 += g_Tpart[base + (size_t)(p + 0) * PART_SZ];
        s1 += g_Tpart[base + (size_t)(p + 1) * PART_SZ];
        s2 += g_Tpart[base + (size_t)(p + 2) * PART_SZ];
        s3 += g_Tpart[base + (size_t)(p + 3) * PART_SZ];
    }
    atomicAdd(&g_T[i], (s0 + s1) + (s2 + s3));
}

// ---------------- K2: split-bf16 mma.sync  Lp = T@W.T - L ----------------
// grid = (VOCAB/128, BATCH/128), 256 threads (8 warps, 2M x 4N).
// Block tile M=128 b, N=128 j, K=64 r. Warp tile 64 x 32.
// D = Thi*Whi^T + Thi*Wlo^T + Tlo*Whi^T (fp32 acc).
// smem tiles [128 rows][64 bf16] = 16 KB each, XOR-swizzled 16B chunks.
#define SM2_TILE 16384
#define SM2_THI  0
#define SM2_TLO  (1 * SM2_TILE)
#define SM2_WHI  (2 * SM2_TILE)
#define SM2_WLO  (3 * SM2_TILE)
#define SM2_TOTAL (4 * SM2_TILE)      // 65536 B

__device__ __forceinline__ unsigned sw_addr(unsigned base, int row, int chunk) {
    return base + row * 128 + ((chunk ^ (row & 7)) << 4);
}

__global__ __launch_bounds__(256, 2) void k_gemm2(const float* __restrict__ L,
                                                  const float* __restrict__ W,
                                                  float* __restrict__ out) {
    extern __shared__ char sm2[];
    const unsigned sb = smem_u32(sm2);
    __shared__ float wred2[8];

    const int tid  = threadIdx.x;
    const int wid  = tid >> 5;
    const int lane = tid & 31;
    const int wm   = wid >> 2;          // 0..1 -> 64 batch rows
    const int wn   = wid & 3;           // 0..3 -> 32 vocab cols
    const int j0   = blockIdx.x * 128;
    const int b0   = blockIdx.y * 128;

    // ---- stage + split T and W tiles into smem ----
#pragma unroll
    for (int it = 0; it < 8; it++) {
        int idx = tid + it * 256;        // 2048 float4
        int row = idx >> 4;
        int rq  = idx & 15;              // float4 within row: 4 floats -> 8 B bf16
        unsigned soff = row * 128 + (((rq >> 1) ^ (row & 7)) << 4) + ((rq & 1) << 3);
        {
            float4 v = *(const float4*)(g_T + (size_t)(b0 + row) * RANK + rq * 4);
            u64 hi, lo; split4(v, hi, lo);
            sts_b64(sb + SM2_THI + soff, hi);
            sts_b64(sb + SM2_TLO + soff, lo);
        }
        {
            float4 v = *(const float4*)(W + (size_t)(j0 + row) * RANK + rq * 4);
            u64 hi, lo; split4(v, hi, lo);
            sts_b64(sb + SM2_WHI + soff, hi);
            sts_b64(sb + SM2_WLO + soff, lo);
        }
    }
    __syncthreads();

    float acc[4][4][4];                 // [mtile][ntile][frag]
#pragma unroll
    for (int mt = 0; mt < 4; mt++)
#pragma unroll
        for (int nt = 0; nt < 4; nt++)
#pragma unroll
            for (int q = 0; q < 4; q++) acc[mt][nt][q] = 0.0f;

    // A fragment address: row = wm*64 + mt*16 + lane%16; chunk = ks*2 + lane/16
    const int arow = wm * 64 + (lane & 15);
    const int achk = lane >> 4;
    // B fragment address: row = wn*32 + nt*8 + lane%8; chunk = ks*2 + (lane/8)&1
    const int brow = wn * 32 + (lane & 7);
    const int bchk = (lane >> 3) & 1;

#pragma unroll
    for (int ks = 0; ks < 4; ks++) {
        unsigned bhi[4][2], blo[4][2];
#pragma unroll
        for (int nt = 0; nt < 4; nt++) {
            unsigned ba = sw_addr(sb, brow + nt * 8, ks * 2 + bchk);
            ldm_x2(ba + SM2_WHI, bhi[nt]);
            ldm_x2(ba + SM2_WLO, blo[nt]);
        }
#pragma unroll
        for (int mt = 0; mt < 4; mt++) {
            unsigned aa = sw_addr(sb, arow + mt * 16, ks * 2 + achk);
            unsigned ahi[4], alo[4];
            ldm_x4(aa + SM2_THI, ahi);
#pragma unroll
            for (int nt = 0; nt < 4; nt++) {
                mma_bf16(acc[mt][nt], ahi, bhi[nt]);   // hi*hi
                mma_bf16(acc[mt][nt], ahi, blo[nt]);   // hi*lo
            }
            ldm_x4(aa + SM2_TLO, alo);
#pragma unroll
            for (int nt = 0; nt < 4; nt++)
                mma_bf16(acc[mt][nt], alo, bhi[nt]);   // lo*hi
        }
    }

    // ---- epilogue: Lp = D - L, write, fused max|Lp| ----
    // acc frag: d0,d1 -> row lane/4,   cols (lane%4)*2, +1
    //           d2,d3 -> row lane/4+8, same cols
    float maxlp = 0.0f;
    const int rbase = b0 + wm * 64 + (lane >> 2);
    const int cbase = j0 + wn * 32 + (lane & 3) * 2;
#pragma unroll
    for (int mt = 0; mt < 4; mt++) {
#pragma unroll
        for (int nt = 0; nt < 4; nt++) {
            const int j = cbase + nt * 8;
            {
                const size_t b = (size_t)(rbase + mt * 16);
                float2 l = *(const float2*)(L + b * VOCAB + j);
                float2 o = { acc[mt][nt][0] - l.x, acc[mt][nt][1] - l.y };
                maxlp = fmaxf(maxlp, fmaxf(fabsf(o.x), fabsf(o.y)));
                *(float2*)(out + b * VOCAB + j) = o;
            }
            {
                const size_t b = (size_t)(rbase + mt * 16 + 8);
                float2 l = *(const float2*)(L + b * VOCAB + j);
                float2 o = { acc[mt][nt][2] - l.x, acc[mt][nt][3] - l.y };
                maxlp = fmaxf(maxlp, fmaxf(fabsf(o.x), fabsf(o.y)));
                *(float2*)(out + b * VOCAB + j) = o;
            }
        }
    }

#pragma unroll
    for (int off = 16; off > 0; off >>= 1)
        maxlp = fmaxf(maxlp, __shfl_xor_sync(0xffffffffu, maxlp, off));
    if (lane == 0) wred2[wid] = maxlp;
    __syncthreads();
    if (tid == 0) {
        float m = wred2[0];
#pragma unroll
        for (int k = 1; k < 8; k++) m = fmaxf(m, wred2[k]);
        atomicMax(&g_maxLp, __float_as_uint(m));
    }
}

// ---------------- K3: out = (1-a)*scale*Lp + a*L ----------------
__global__ void k_final(const float* __restrict__ L, float* __restrict__ out) {
    const float maxl  = __uint_as_float(g_maxL);
    const float maxlp = __uint_as_float(g_maxLp);
    const float scale = maxl / fmaxf(maxlp, EPSF);
    const float c2 = (1.0f - ALPHA) * scale;

    const int n4 = BATCH * VOCAB / 4;
    float4* o4 = (float4*)out;
    const float4* l4 = (const float4*)L;
    for (int i = blockIdx.x * blockDim.x + threadIdx.x; i < n4;
         i += gridDim.x * blockDim.x) {
        float4 o = o4[i];
        float4 l = l4[i];
        o.x = fmaf(c2, o.x, ALPHA * l.x);
        o.y = fmaf(c2, o.y, ALPHA * l.y);
        o.z = fmaf(c2, o.z, ALPHA * l.z);
        o.w = fmaf(c2, o.w, ALPHA * l.w);
        o4[i] = o;
    }
}

// ---------------- launch ----------------
extern "C" void kernel_launch(void* const* d_in, const int* in_sizes, int n_in,
                              void* d_out, int out_size) {
    const float* L = nullptr;
    const float* W = nullptr;
    for (int i = 0; i < n_in; i++) {
        if (in_sizes[i] == BATCH * VOCAB)     L = (const float*)d_in[i];
        else if (in_sizes[i] == VOCAB * RANK) W = (const float*)d_in[i];
    }
    if (!L && n_in >= 2) L = (const float*)d_in[1];
    if (!W && n_in >= 3) W = (const float*)d_in[2];
    float* out = (float*)d_out;

    cudaFuncSetAttribute(k_gemm1, cudaFuncAttributeMaxDynamicSharedMemorySize,
                         G1_SMEM);
    cudaFuncSetAttribute(k_gemm2, cudaFuncAttributeMaxDynamicSharedMemorySize,
                         SM2_TOTAL);

    k_init<<<(BATCH * RANK) / 256, 256>>>();
    k_gemm1<<<dim3(NKC, 2), 256, G1_SMEM>>>(L, W);
    k_red<<<dim3((BATCH * RANK) / 256, KGRP), 256>>>();
    k_gemm2<<<dim3(VOCAB / 128, BATCH / 128), 256, SM2_TOTAL>>>(L, W, out);
    k_final<<<4000, 256>>>(L, out);
}

// round 12
// speedup vs baseline: 1.3815x; 1.1696x over previous
#include <cuda_runtime.h>
#include <cstdint>

#define BATCH 256
#define VOCAB 128000
#define RANK  64
#define ALPHA 0.4f
#define EPSF  1.1920928955078125e-07f   // np.finfo(float32).eps

#define KC1   256                // k-chunk per gemm1 block
#define NKC1  (VOCAB / KC1)      // 500 k-chunks
#define PART_SZ (128 * RANK)     // 8192 floats per partial

// ---------------- scratch (no allocations allowed) ----------------
__device__ float        g_Tpart[2 * NKC1 * PART_SZ];  // per-block partial T (33 MB)
__device__ float        g_T[BATCH * RANK];            // reduced T = L @ W
__device__ unsigned int g_maxL;                       // float bits of max|L|
__device__ unsigned int g_maxLp;                      // float bits of max|Lp_raw|

// ---------------- PTX helpers ----------------
typedef unsigned long long u64;

__device__ __forceinline__ unsigned smem_u32(const void* p) {
    unsigned a;
    asm("{ .reg .u64 t; cvta.to.shared.u64 t, %1; cvt.u32.u64 %0, t; }"
        : "=r"(a) : "l"(p));
    return a;
}
__device__ __forceinline__ void sts_b64(unsigned a, u64 v) {
    asm volatile("st.shared.b64 [%0], %1;" :: "r"(a), "l"(v));
}

// ldmatrix (sm_75+, valid on compute_103)
__device__ __forceinline__ void ldm_x4(unsigned addr, unsigned* r) {
    asm volatile("ldmatrix.sync.aligned.m8n8.x4.shared.b16 {%0,%1,%2,%3}, [%4];"
                 : "=r"(r[0]), "=r"(r[1]), "=r"(r[2]), "=r"(r[3]) : "r"(addr));
}
__device__ __forceinline__ void ldm_x4t(unsigned addr, unsigned* r) {
    asm volatile("ldmatrix.sync.aligned.m8n8.x4.trans.shared.b16 {%0,%1,%2,%3}, [%4];"
                 : "=r"(r[0]), "=r"(r[1]), "=r"(r[2]), "=r"(r[3]) : "r"(addr));
}
__device__ __forceinline__ void ldm_x2(unsigned addr, unsigned* r) {
    asm volatile("ldmatrix.sync.aligned.m8n8.x2.shared.b16 {%0,%1}, [%2];"
                 : "=r"(r[0]), "=r"(r[1]) : "r"(addr));
}
// bf16 mma (sm_80+, valid on compute_103)
__device__ __forceinline__ void mma_bf16(float* c, const unsigned* a, const unsigned* b) {
    asm volatile(
        "mma.sync.aligned.m16n8k16.row.col.f32.bf16.bf16.f32 "
        "{%0,%1,%2,%3}, {%4,%5,%6,%7}, {%8,%9}, {%0,%1,%2,%3};"
        : "+f"(c[0]), "+f"(c[1]), "+f"(c[2]), "+f"(c[3])
        : "r"(a[0]), "r"(a[1]), "r"(a[2]), "r"(a[3]), "r"(b[0]), "r"(b[1]));
}

// fp32 -> (hi,lo) bf16 split of a float4; each u64 = 4 packed bf16 in element order
__device__ __forceinline__ void split4(float4 v, u64& hi, u64& lo) {
    unsigned h01, h23, l01, l23;
    asm("cvt.rn.bf16x2.f32 %0, %1, %2;" : "=r"(h01) : "f"(v.y), "f"(v.x));
    asm("cvt.rn.bf16x2.f32 %0, %1, %2;" : "=r"(h23) : "f"(v.w), "f"(v.z));
    float hx = __uint_as_float(h01 << 16);
    float hy = __uint_as_float(h01 & 0xffff0000u);
    float hz = __uint_as_float(h23 << 16);
    float hw = __uint_as_float(h23 & 0xffff0000u);
    asm("cvt.rn.bf16x2.f32 %0, %1, %2;" : "=r"(l01) : "f"(v.y - hy), "f"(v.x - hx));
    asm("cvt.rn.bf16x2.f32 %0, %1, %2;" : "=r"(l23) : "f"(v.w - hw), "f"(v.z - hz));
    hi = (u64)h01 | ((u64)h23 << 32);
    lo = (u64)l01 | ((u64)l23 << 32);
}

// ---------------- K0: init g_T + maxima ----------------
__global__ void k_init() {
    int i = blockIdx.x * blockDim.x + threadIdx.x;
    if (i < BATCH * RANK) g_T[i] = 0.0f;
    if (i == 0) { g_maxL = 0u; g_maxLp = 0u; }
}

// ---------------- K1: partial T = L@W via split-bf16 mma.sync, fused max|L| ----------
// grid = (NKC1, 2 batch-halves), 256 threads (8 warps). Block tile 128 b x 64 r x 256 k.
// Warp tile 16 b x 64 r. D = Lhi*Whi + Lhi*Wlo + Llo*Whi (fp32 acc).
// smem: L tiles [128 b][64 k] bf16 hi/lo (16 KB each); W tiles [64 k][64 r] bf16 hi/lo
// (8 KB each), all XOR-swizzled 16B chunks. W B-fragments come via ldmatrix.trans.
#define G1_LHI 0
#define G1_LLO 16384
#define G1_WHI 32768
#define G1_WLO 40960
#define G1_TOTAL 49152

__global__ __launch_bounds__(256, 3) void k_gemm1(const float* __restrict__ L,
                                                  const float* __restrict__ W) {
    extern __shared__ char sm1[];
    const unsigned sb = smem_u32(sm1);
    __shared__ float wred[8];

    const int tid  = threadIdx.x;
    const int wid  = tid >> 5;
    const int lane = tid & 31;
    const int k0blk = blockIdx.x * KC1;
    const int b0    = blockIdx.y * 128;

    float acc[8][4];                 // 8 n-tiles (r), 4 frags each
#pragma unroll
    for (int nt = 0; nt < 8; nt++)
#pragma unroll
        for (int q = 0; q < 4; q++) acc[nt][q] = 0.0f;

    float maxl = 0.0f;

    for (int kt = 0; kt < KC1; kt += 64) {
        const int k0 = k0blk + kt;
        __syncthreads();
        // stage L [128 b][64 k] -> hi/lo, swizzled; fused abs-max
#pragma unroll
        for (int it = 0; it < 8; it++) {
            int idx = tid + it * 256;        // 2048 float4
            int row = idx >> 4;
            int kq  = idx & 15;
            float4 v = *(const float4*)(L + (size_t)(b0 + row) * VOCAB + k0 + kq * 4);
            maxl = fmaxf(maxl, fmaxf(fmaxf(fabsf(v.x), fabsf(v.y)),
                                     fmaxf(fabsf(v.z), fabsf(v.w))));
            unsigned soff = row * 128 + (((kq >> 1) ^ (row & 7)) << 4) + ((kq & 1) << 3);
            u64 hi, lo; split4(v, hi, lo);
            sts_b64(sb + G1_LHI + soff, hi);
            sts_b64(sb + G1_LLO + soff, lo);
        }
        // stage W [64 k][64 r] -> hi/lo, swizzled (natural k-row order)
#pragma unroll
        for (int it = 0; it < 4; it++) {
            int idx = tid + it * 256;        // 1024 float4
            int krow = idx >> 4;
            int rq   = idx & 15;
            float4 v = *(const float4*)(W + (size_t)(k0 + krow) * RANK + rq * 4);
            unsigned soff = krow * 128 + (((rq >> 1) ^ (krow & 7)) << 4) + ((rq & 1) << 3);
            u64 hi, lo; split4(v, hi, lo);
            sts_b64(sb + G1_WHI + soff, hi);
            sts_b64(sb + G1_WLO + soff, lo);
        }
        __syncthreads();

#pragma unroll
        for (int ks = 0; ks < 4; ks++) {
            // A (L) fragment: rows wid*16 + lane%16, chunk = ks*2 + lane/16
            const int arow = wid * 16 + (lane & 15);
            const unsigned aaddr = sb + arow * 128 +
                (((ks * 2 + (lane >> 4)) ^ (arow & 7)) << 4);
            // B (W^T) via ldmatrix.trans on [k][r] storage:
            // lane groups map to (k-half, r-block): kloc = ks*16 + lane%16,
            // chunk c = nt2*2 + lane/16
            const int kloc = ks * 16 + (lane & 15);
            unsigned ahi[4], alo[4];
            unsigned bhi[4][4];              // 4 pairs of n-tiles
#pragma unroll
            for (int nt2 = 0; nt2 < 4; nt2++) {
                unsigned baddr = sb + kloc * 128 +
                    (((nt2 * 2 + (lane >> 4)) ^ (lane & 7)) << 4);
                ldm_x4t(baddr + G1_WHI, bhi[nt2]);
            }
            ldm_x4(aaddr + G1_LHI, ahi);
#pragma unroll
            for (int nt2 = 0; nt2 < 4; nt2++) {
                mma_bf16(acc[nt2 * 2 + 0], ahi, bhi[nt2] + 0);   // hi*hi
                mma_bf16(acc[nt2 * 2 + 1], ahi, bhi[nt2] + 2);
            }
#pragma unroll
            for (int nt2 = 0; nt2 < 4; nt2++) {                  // hi*lo
                unsigned blo[4];
                unsigned baddr = sb + kloc * 128 +
                    (((nt2 * 2 + (lane >> 4)) ^ (lane & 7)) << 4);
                ldm_x4t(baddr + G1_WLO, blo);
                mma_bf16(acc[nt2 * 2 + 0], ahi, blo + 0);
                mma_bf16(acc[nt2 * 2 + 1], ahi, blo + 2);
            }
            ldm_x4(aaddr + G1_LLO, alo);
#pragma unroll
            for (int nt2 = 0; nt2 < 4; nt2++) {                  // lo*hi
                mma_bf16(acc[nt2 * 2 + 0], alo, bhi[nt2] + 0);
                mma_bf16(acc[nt2 * 2 + 1], alo, bhi[nt2] + 2);
            }
        }
    }

    // write per-block partial tile [128 b][64 r] (float2 stores)
    {
        float* dst = g_Tpart + (size_t)(blockIdx.y * NKC1 + blockIdx.x) * PART_SZ;
        const int r0 = (lane & 3) * 2;
        const int rowA = wid * 16 + (lane >> 2);
#pragma unroll
        for (int nt = 0; nt < 8; nt++) {
            int c = nt * 8 + r0;
            *(float2*)(dst + rowA * RANK + c)       = make_float2(acc[nt][0], acc[nt][1]);
            *(float2*)(dst + (rowA + 8) * RANK + c) = make_float2(acc[nt][2], acc[nt][3]);
        }
    }

    // block-reduce max|L|
#pragma unroll
    for (int off = 16; off > 0; off >>= 1)
        maxl = fmaxf(maxl, __shfl_xor_sync(0xffffffffu, maxl, off));
    if (lane == 0) wred[wid] = maxl;
    __syncthreads();
    if (tid == 0) {
        float m = wred[0];
#pragma unroll
        for (int k = 1; k < 8; k++) m = fmaxf(m, wred[k]);
        atomicMax(&g_maxL, __float_as_uint(m));
    }
}

// ---------------- K1b: reduce partials -> g_T ----------------
#define KGRP 10
#define KPER (NKC1 / KGRP)       // 50
__global__ void k_red() {
    const int i = blockIdx.x * blockDim.x + threadIdx.x;   // (b,r) flat, 16384
    const int b = i >> 6;
    const int r = i & 63;
    const int half = b >> 7;
    const size_t off = (size_t)(b & 127) * RANK + r;
    const size_t base = ((size_t)half * NKC1 + blockIdx.y * KPER) * PART_SZ + off;

    float s0 = 0.f, s1 = 0.f;
#pragma unroll 2
    for (int p = 0; p < KPER; p += 2) {
        s0 += g_Tpart[base + (size_t)(p + 0) * PART_SZ];
        s1 += g_Tpart[base + (size_t)(p + 1) * PART_SZ];
    }
    atomicAdd(&g_T[i], s0 + s1);
}

// ---------------- K2: split-bf16 mma.sync  Lp = T@W.T - L ----------------
// grid = (VOCAB/128, BATCH/128), 256 threads (8 warps, 2M x 4N).
#define SM2_TILE 16384
#define SM2_THI  0
#define SM2_TLO  (1 * SM2_TILE)
#define SM2_WHI  (2 * SM2_TILE)
#define SM2_WLO  (3 * SM2_TILE)
#define SM2_TOTAL (4 * SM2_TILE)      // 65536 B

__device__ __forceinline__ unsigned sw_addr(unsigned base, int row, int chunk) {
    return base + row * 128 + ((chunk ^ (row & 7)) << 4);
}

__global__ __launch_bounds__(256, 2) void k_gemm2(const float* __restrict__ L,
                                                  const float* __restrict__ W,
                                                  float* __restrict__ out) {
    extern __shared__ char sm2[];
    const unsigned sb = smem_u32(sm2);
    __shared__ float wred2[8];

    const int tid  = threadIdx.x;
    const int wid  = tid >> 5;
    const int lane = tid & 31;
    const int wm   = wid >> 2;
    const int wn   = wid & 3;
    const int j0   = blockIdx.x * 128;
    const int b0   = blockIdx.y * 128;

#pragma unroll
    for (int it = 0; it < 8; it++) {
        int idx = tid + it * 256;
        int row = idx >> 4;
        int rq  = idx & 15;
        unsigned soff = row * 128 + (((rq >> 1) ^ (row & 7)) << 4) + ((rq & 1) << 3);
        {
            float4 v = *(const float4*)(g_T + (size_t)(b0 + row) * RANK + rq * 4);
            u64 hi, lo; split4(v, hi, lo);
            sts_b64(sb + SM2_THI + soff, hi);
            sts_b64(sb + SM2_TLO + soff, lo);
        }
        {
            float4 v = *(const float4*)(W + (size_t)(j0 + row) * RANK + rq * 4);
            u64 hi, lo; split4(v, hi, lo);
            sts_b64(sb + SM2_WHI + soff, hi);
            sts_b64(sb + SM2_WLO + soff, lo);
        }
    }
    __syncthreads();

    float acc[4][4][4];
#pragma unroll
    for (int mt = 0; mt < 4; mt++)
#pragma unroll
        for (int nt = 0; nt < 4; nt++)
#pragma unroll
            for (int q = 0; q < 4; q++) acc[mt][nt][q] = 0.0f;

    const int arow = wm * 64 + (lane & 15);
    const int achk = lane >> 4;
    const int brow = wn * 32 + (lane & 7);
    const int bchk = (lane >> 3) & 1;

#pragma unroll
    for (int ks = 0; ks < 4; ks++) {
        unsigned bhi[4][2], blo[4][2];
#pragma unroll
        for (int nt = 0; nt < 4; nt++) {
            unsigned ba = sw_addr(sb, brow + nt * 8, ks * 2 + bchk);
            ldm_x2(ba + SM2_WHI, bhi[nt]);
            ldm_x2(ba + SM2_WLO, blo[nt]);
        }
#pragma unroll
        for (int mt = 0; mt < 4; mt++) {
            unsigned aa = sw_addr(sb, arow + mt * 16, ks * 2 + achk);
            unsigned ahi[4], alo[4];
            ldm_x4(aa + SM2_THI, ahi);
#pragma unroll
            for (int nt = 0; nt < 4; nt++) {
                mma_bf16(acc[mt][nt], ahi, bhi[nt]);
                mma_bf16(acc[mt][nt], ahi, blo[nt]);
            }
            ldm_x4(aa + SM2_TLO, alo);
#pragma unroll
            for (int nt = 0; nt < 4; nt++)
                mma_bf16(acc[mt][nt], alo, bhi[nt]);
        }
    }

    float maxlp = 0.0f;
    const int rbase = b0 + wm * 64 + (lane >> 2);
    const int cbase = j0 + wn * 32 + (lane & 3) * 2;
#pragma unroll
    for (int mt = 0; mt < 4; mt++) {
#pragma unroll
        for (int nt = 0; nt < 4; nt++) {
            const int j = cbase + nt * 8;
            {
                const size_t b = (size_t)(rbase + mt * 16);
                float2 l = *(const float2*)(L + b * VOCAB + j);
                float2 o = { acc[mt][nt][0] - l.x, acc[mt][nt][1] - l.y };
                maxlp = fmaxf(maxlp, fmaxf(fabsf(o.x), fabsf(o.y)));
                *(float2*)(out + b * VOCAB + j) = o;
            }
            {
                const size_t b = (size_t)(rbase + mt * 16 + 8);
                float2 l = *(const float2*)(L + b * VOCAB + j);
                float2 o = { acc[mt][nt][2] - l.x, acc[mt][nt][3] - l.y };
                maxlp = fmaxf(maxlp, fmaxf(fabsf(o.x), fabsf(o.y)));
                *(float2*)(out + b * VOCAB + j) = o;
            }
        }
    }

#pragma unroll
    for (int off = 16; off > 0; off >>= 1)
        maxlp = fmaxf(maxlp, __shfl_xor_sync(0xffffffffu, maxlp, off));
    if (lane == 0) wred2[wid] = maxlp;
    __syncthreads();
    if (tid == 0) {
        float m = wred2[0];
#pragma unroll
        for (int k = 1; k < 8; k++) m = fmaxf(m, wred2[k]);
        atomicMax(&g_maxLp, __float_as_uint(m));
    }
}

// ---------------- K3: out = (1-a)*scale*Lp + a*L ----------------
__global__ void k_final(const float* __restrict__ L, float* __restrict__ out) {
    const float maxl  = __uint_as_float(g_maxL);
    const float maxlp = __uint_as_float(g_maxLp);
    const float scale = maxl / fmaxf(maxlp, EPSF);
    const float c2 = (1.0f - ALPHA) * scale;

    const int n4 = BATCH * VOCAB / 4;
    float4* o4 = (float4*)out;
    const float4* l4 = (const float4*)L;
    for (int i = blockIdx.x * blockDim.x + threadIdx.x; i < n4;
         i += gridDim.x * blockDim.x) {
        float4 o = o4[i];
        float4 l = l4[i];
        o.x = fmaf(c2, o.x, ALPHA * l.x);
        o.y = fmaf(c2, o.y, ALPHA * l.y);
        o.z = fmaf(c2, o.z, ALPHA * l.z);
        o.w = fmaf(c2, o.w, ALPHA * l.w);
        o4[i] = o;
    }
}

// ---------------- launch ----------------
extern "C" void kernel_launch(void* const* d_in, const int* in_sizes, int n_in,
                              void* d_out, int out_size) {
    const float* L = nullptr;
    const float* W = nullptr;
    for (int i = 0; i < n_in; i++) {
        if (in_sizes[i] == BATCH * VOCAB)     L = (const float*)d_in[i];
        else if (in_sizes[i] == VOCAB * RANK) W = (const float*)d_in[i];
    }
    if (!L && n_in >= 2) L = (const float*)d_in[1];
    if (!W && n_in >= 3) W = (const float*)d_in[2];
    float* out = (float*)d_out;

    cudaFuncSetAttribute(k_gemm1, cudaFuncAttributeMaxDynamicSharedMemorySize,
                         G1_TOTAL);
    cudaFuncSetAttribute(k_gemm2, cudaFuncAttributeMaxDynamicSharedMemorySize,
                         SM2_TOTAL);

    k_init<<<(BATCH * RANK) / 256, 256>>>();
    k_gemm1<<<dim3(NKC1, 2), 256, G1_TOTAL>>>(L, W);
    k_red<<<dim3((BATCH * RANK) / 256, KGRP), 256>>>();
    k_gemm2<<<dim3(VOCAB / 128, BATCH / 128), 256, SM2_TOTAL>>>(L, W, out);
    k_final<<<4000, 256>>>(L, out);
}

// round 13
// speedup vs baseline: 1.4142x; 1.0237x over previous
#include <cuda_runtime.h>
#include <cstdint>

#define BATCH 256
#define VOCAB 128000
#define RANK  64
#define ALPHA 0.4f
#define EPSF  1.1920928955078125e-07f   // np.finfo(float32).eps

#define KC1   256                // k-chunk per gemm1 block
#define NKC1  (VOCAB / KC1)      // 500 k-chunks
#define PART_SZ (128 * RANK)     // 8192 floats per partial

// ---------------- scratch (no allocations allowed) ----------------
__device__ float        g_Tpart[2 * NKC1 * PART_SZ];  // per-block partial T (33 MB)
__device__ float        g_T[BATCH * RANK];            // reduced T = L @ W
__device__ unsigned int g_maxL;                       // float bits of max|L|
__device__ unsigned int g_maxLp;                      // float bits of max|Lp_raw|

// ---------------- PTX helpers ----------------
typedef unsigned long long u64;

__device__ __forceinline__ unsigned smem_u32(const void* p) {
    unsigned a;
    asm("{ .reg .u64 t; cvta.to.shared.u64 t, %1; cvt.u32.u64 %0, t; }"
        : "=r"(a) : "l"(p));
    return a;
}
__device__ __forceinline__ void sts_b64(unsigned a, u64 v) {
    asm volatile("st.shared.b64 [%0], %1;" :: "r"(a), "l"(v));
}

// ldmatrix (sm_75+, valid on compute_103)
__device__ __forceinline__ void ldm_x4(unsigned addr, unsigned* r) {
    asm volatile("ldmatrix.sync.aligned.m8n8.x4.shared.b16 {%0,%1,%2,%3}, [%4];"
                 : "=r"(r[0]), "=r"(r[1]), "=r"(r[2]), "=r"(r[3]) : "r"(addr));
}
__device__ __forceinline__ void ldm_x4t(unsigned addr, unsigned* r) {
    asm volatile("ldmatrix.sync.aligned.m8n8.x4.trans.shared.b16 {%0,%1,%2,%3}, [%4];"
                 : "=r"(r[0]), "=r"(r[1]), "=r"(r[2]), "=r"(r[3]) : "r"(addr));
}
__device__ __forceinline__ void ldm_x2(unsigned addr, unsigned* r) {
    asm volatile("ldmatrix.sync.aligned.m8n8.x2.shared.b16 {%0,%1}, [%2];"
                 : "=r"(r[0]), "=r"(r[1]) : "r"(addr));
}
// bf16 mma (sm_80+, valid on compute_103)
__device__ __forceinline__ void mma_bf16(float* c, const unsigned* a, const unsigned* b) {
    asm volatile(
        "mma.sync.aligned.m16n8k16.row.col.f32.bf16.bf16.f32 "
        "{%0,%1,%2,%3}, {%4,%5,%6,%7}, {%8,%9}, {%0,%1,%2,%3};"
        : "+f"(c[0]), "+f"(c[1]), "+f"(c[2]), "+f"(c[3])
        : "r"(a[0]), "r"(a[1]), "r"(a[2]), "r"(a[3]), "r"(b[0]), "r"(b[1]));
}

// fp32 -> (hi,lo) bf16 split of a float4; each u64 = 4 packed bf16 in element order
__device__ __forceinline__ void split4(float4 v, u64& hi, u64& lo) {
    unsigned h01, h23, l01, l23;
    asm("cvt.rn.bf16x2.f32 %0, %1, %2;" : "=r"(h01) : "f"(v.y), "f"(v.x));
    asm("cvt.rn.bf16x2.f32 %0, %1, %2;" : "=r"(h23) : "f"(v.w), "f"(v.z));
    float hx = __uint_as_float(h01 << 16);
    float hy = __uint_as_float(h01 & 0xffff0000u);
    float hz = __uint_as_float(h23 << 16);
    float hw = __uint_as_float(h23 & 0xffff0000u);
    asm("cvt.rn.bf16x2.f32 %0, %1, %2;" : "=r"(l01) : "f"(v.y - hy), "f"(v.x - hx));
    asm("cvt.rn.bf16x2.f32 %0, %1, %2;" : "=r"(l23) : "f"(v.w - hw), "f"(v.z - hz));
    hi = (u64)h01 | ((u64)h23 << 32);
    lo = (u64)l01 | ((u64)l23 << 32);
}

// ---------------- K0: init g_T + maxima ----------------
__global__ void k_init() {
    int i = blockIdx.x * blockDim.x + threadIdx.x;
    if (i < BATCH * RANK) g_T[i] = 0.0f;
    if (i == 0) { g_maxL = 0u; g_maxLp = 0u; }
}

// ---------------- K1: partial T = L@W via split-bf16 mma.sync, fused max|L| ----------
// grid = (NKC1, 2 batch-halves), 256 threads (8 warps). Block tile 128 b x 64 r x 256 k.
#define G1_LHI 0
#define G1_LLO 16384
#define G1_WHI 32768
#define G1_WLO 40960
#define G1_TOTAL 49152

__global__ __launch_bounds__(256, 3) void k_gemm1(const float* __restrict__ L,
                                                  const float* __restrict__ W) {
    extern __shared__ char sm1[];
    const unsigned sb = smem_u32(sm1);
    __shared__ float wred[8];

    const int tid  = threadIdx.x;
    const int wid  = tid >> 5;
    const int lane = tid & 31;
    const int k0blk = blockIdx.x * KC1;
    const int b0    = blockIdx.y * 128;

    float acc[8][4];
#pragma unroll
    for (int nt = 0; nt < 8; nt++)
#pragma unroll
        for (int q = 0; q < 4; q++) acc[nt][q] = 0.0f;

    float maxl = 0.0f;

    for (int kt = 0; kt < KC1; kt += 64) {
        const int k0 = k0blk + kt;
        __syncthreads();
#pragma unroll
        for (int it = 0; it < 8; it++) {
            int idx = tid + it * 256;
            int row = idx >> 4;
            int kq  = idx & 15;
            float4 v = *(const float4*)(L + (size_t)(b0 + row) * VOCAB + k0 + kq * 4);
            maxl = fmaxf(maxl, fmaxf(fmaxf(fabsf(v.x), fabsf(v.y)),
                                     fmaxf(fabsf(v.z), fabsf(v.w))));
            unsigned soff = row * 128 + (((kq >> 1) ^ (row & 7)) << 4) + ((kq & 1) << 3);
            u64 hi, lo; split4(v, hi, lo);
            sts_b64(sb + G1_LHI + soff, hi);
            sts_b64(sb + G1_LLO + soff, lo);
        }
#pragma unroll
        for (int it = 0; it < 4; it++) {
            int idx = tid + it * 256;
            int krow = idx >> 4;
            int rq   = idx & 15;
            float4 v = *(const float4*)(W + (size_t)(k0 + krow) * RANK + rq * 4);
            unsigned soff = krow * 128 + (((rq >> 1) ^ (krow & 7)) << 4) + ((rq & 1) << 3);
            u64 hi, lo; split4(v, hi, lo);
            sts_b64(sb + G1_WHI + soff, hi);
            sts_b64(sb + G1_WLO + soff, lo);
        }
        __syncthreads();

#pragma unroll
        for (int ks = 0; ks < 4; ks++) {
            const int arow = wid * 16 + (lane & 15);
            const unsigned aaddr = sb + arow * 128 +
                (((ks * 2 + (lane >> 4)) ^ (arow & 7)) << 4);
            const int kloc = ks * 16 + (lane & 15);
            unsigned ahi[4], alo[4];
            unsigned bhi[4][4];
#pragma unroll
            for (int nt2 = 0; nt2 < 4; nt2++) {
                unsigned baddr = sb + kloc * 128 +
                    (((nt2 * 2 + (lane >> 4)) ^ (lane & 7)) << 4);
                ldm_x4t(baddr + G1_WHI, bhi[nt2]);
            }
            ldm_x4(aaddr + G1_LHI, ahi);
#pragma unroll
            for (int nt2 = 0; nt2 < 4; nt2++) {
                mma_bf16(acc[nt2 * 2 + 0], ahi, bhi[nt2] + 0);
                mma_bf16(acc[nt2 * 2 + 1], ahi, bhi[nt2] + 2);
            }
#pragma unroll
            for (int nt2 = 0; nt2 < 4; nt2++) {
                unsigned blo[4];
                unsigned baddr = sb + kloc * 128 +
                    (((nt2 * 2 + (lane >> 4)) ^ (lane & 7)) << 4);
                ldm_x4t(baddr + G1_WLO, blo);
                mma_bf16(acc[nt2 * 2 + 0], ahi, blo + 0);
                mma_bf16(acc[nt2 * 2 + 1], ahi, blo + 2);
            }
            ldm_x4(aaddr + G1_LLO, alo);
#pragma unroll
            for (int nt2 = 0; nt2 < 4; nt2++) {
                mma_bf16(acc[nt2 * 2 + 0], alo, bhi[nt2] + 0);
                mma_bf16(acc[nt2 * 2 + 1], alo, bhi[nt2] + 2);
            }
        }
    }

    {
        float* dst = g_Tpart + (size_t)(blockIdx.y * NKC1 + blockIdx.x) * PART_SZ;
        const int r0 = (lane & 3) * 2;
        const int rowA = wid * 16 + (lane >> 2);
#pragma unroll
        for (int nt = 0; nt < 8; nt++) {
            int c = nt * 8 + r0;
            *(float2*)(dst + rowA * RANK + c)       = make_float2(acc[nt][0], acc[nt][1]);
            *(float2*)(dst + (rowA + 8) * RANK + c) = make_float2(acc[nt][2], acc[nt][3]);
        }
    }

#pragma unroll
    for (int off = 16; off > 0; off >>= 1)
        maxl = fmaxf(maxl, __shfl_xor_sync(0xffffffffu, maxl, off));
    if (lane == 0) wred[wid] = maxl;
    __syncthreads();
    if (tid == 0) {
        float m = wred[0];
#pragma unroll
        for (int k = 1; k < 8; k++) m = fmaxf(m, wred[k]);
        atomicMax(&g_maxL, __float_as_uint(m));
    }
}

// ---------------- K1b: reduce partials -> g_T ----------------
#define KGRP 10
#define KPER (NKC1 / KGRP)       // 50
__global__ void k_red() {
    const int i = blockIdx.x * blockDim.x + threadIdx.x;
    const int b = i >> 6;
    const int r = i & 63;
    const int half = b >> 7;
    const size_t off = (size_t)(b & 127) * RANK + r;
    const size_t base = ((size_t)half * NKC1 + blockIdx.y * KPER) * PART_SZ + off;

    float s0 = 0.f, s1 = 0.f;
#pragma unroll 2
    for (int p = 0; p < KPER; p += 2) {
        s0 += g_Tpart[base + (size_t)(p + 0) * PART_SZ];
        s1 += g_Tpart[base + (size_t)(p + 1) * PART_SZ];
    }
    atomicAdd(&g_T[i], s0 + s1);
}

// ---------------- K2: two-pass split-bf16 mma.sync over D = T@W.T ----------------
// Pass A (WRITE=false): maxLp = max|D - L|, no stores.
// Pass B (WRITE=true):  out   = c2*D + (alpha - c2)*L,  c2 = 0.6*maxL/max(maxLp,eps).
// grid = (VOCAB/128, BATCH/128), 256 threads (8 warps, 2M x 4N).
#define SM2_TILE 16384
#define SM2_THI  0
#define SM2_TLO  (1 * SM2_TILE)
#define SM2_WHI  (2 * SM2_TILE)
#define SM2_WLO  (3 * SM2_TILE)
#define SM2_TOTAL (4 * SM2_TILE)      // 65536 B

__device__ __forceinline__ unsigned sw_addr(unsigned base, int row, int chunk) {
    return base + row * 128 + ((chunk ^ (row & 7)) << 4);
}

template <bool WRITE>
__global__ __launch_bounds__(256, 2) void k_pass(const float* __restrict__ L,
                                                 const float* __restrict__ W,
                                                 float* __restrict__ out) {
    extern __shared__ char sm2[];
    const unsigned sb = smem_u32(sm2);
    __shared__ float wred2[8];

    const int tid  = threadIdx.x;
    const int wid  = tid >> 5;
    const int lane = tid & 31;
    const int wm   = wid >> 2;
    const int wn   = wid & 3;
    const int j0   = blockIdx.x * 128;
    const int b0   = blockIdx.y * 128;

#pragma unroll
    for (int it = 0; it < 8; it++) {
        int idx = tid + it * 256;
        int row = idx >> 4;
        int rq  = idx & 15;
        unsigned soff = row * 128 + (((rq >> 1) ^ (row & 7)) << 4) + ((rq & 1) << 3);
        {
            float4 v = *(const float4*)(g_T + (size_t)(b0 + row) * RANK + rq * 4);
            u64 hi, lo; split4(v, hi, lo);
            sts_b64(sb + SM2_THI + soff, hi);
            sts_b64(sb + SM2_TLO + soff, lo);
        }
        {
            float4 v = *(const float4*)(W + (size_t)(j0 + row) * RANK + rq * 4);
            u64 hi, lo; split4(v, hi, lo);
            sts_b64(sb + SM2_WHI + soff, hi);
            sts_b64(sb + SM2_WLO + soff, lo);
        }
    }
    __syncthreads();

    float acc[4][4][4];
#pragma unroll
    for (int mt = 0; mt < 4; mt++)
#pragma unroll
        for (int nt = 0; nt < 4; nt++)
#pragma unroll
            for (int q = 0; q < 4; q++) acc[mt][nt][q] = 0.0f;

    const int arow = wm * 64 + (lane & 15);
    const int achk = lane >> 4;
    const int brow = wn * 32 + (lane & 7);
    const int bchk = (lane >> 3) & 1;

#pragma unroll
    for (int ks = 0; ks < 4; ks++) {
        unsigned bhi[4][2], blo[4][2];
#pragma unroll
        for (int nt = 0; nt < 4; nt++) {
            unsigned ba = sw_addr(sb, brow + nt * 8, ks * 2 + bchk);
            ldm_x2(ba + SM2_WHI, bhi[nt]);
            ldm_x2(ba + SM2_WLO, blo[nt]);
        }
#pragma unroll
        for (int mt = 0; mt < 4; mt++) {
            unsigned aa = sw_addr(sb, arow + mt * 16, ks * 2 + achk);
            unsigned ahi[4], alo[4];
            ldm_x4(aa + SM2_THI, ahi);
#pragma unroll
            for (int nt = 0; nt < 4; nt++) {
                mma_bf16(acc[mt][nt], ahi, bhi[nt]);
                mma_bf16(acc[mt][nt], ahi, blo[nt]);
            }
            ldm_x4(aa + SM2_TLO, alo);
#pragma unroll
            for (int nt = 0; nt < 4; nt++)
                mma_bf16(acc[mt][nt], alo, bhi[nt]);
        }
    }

    // epilogue
    float c2 = 0.0f, c3 = 0.0f;
    if (WRITE) {
        const float maxl  = __uint_as_float(g_maxL);
        const float maxlp = __uint_as_float(g_maxLp);
        const float s = maxl / fmaxf(maxlp, EPSF);
        c2 = (1.0f - ALPHA) * s;        // multiplies D
        c3 = ALPHA - c2;                // multiplies L
    }
    float maxlp_loc = 0.0f;
    const int rbase = b0 + wm * 64 + (lane >> 2);
    const int cbase = j0 + wn * 32 + (lane & 3) * 2;
#pragma unroll
    for (int mt = 0; mt < 4; mt++) {
#pragma unroll
        for (int nt = 0; nt < 4; nt++) {
            const int j = cbase + nt * 8;
#pragma unroll
            for (int h = 0; h < 2; h++) {
                const size_t b = (size_t)(rbase + mt * 16 + h * 8);
                float2 l = *(const float2*)(L + b * VOCAB + j);
                float dx = acc[mt][nt][h * 2 + 0];
                float dy = acc[mt][nt][h * 2 + 1];
                if (WRITE) {
                    float2 o = { fmaf(c2, dx, c3 * l.x), fmaf(c2, dy, c3 * l.y) };
                    *(float2*)(out + b * VOCAB + j) = o;
                } else {
                    maxlp_loc = fmaxf(maxlp_loc,
                                      fmaxf(fabsf(dx - l.x), fabsf(dy - l.y)));
                }
            }
        }
    }

    if (!WRITE) {
#pragma unroll
        for (int off = 16; off > 0; off >>= 1)
            maxlp_loc = fmaxf(maxlp_loc, __shfl_xor_sync(0xffffffffu, maxlp_loc, off));
        if (lane == 0) wred2[wid] = maxlp_loc;
        __syncthreads();
        if (tid == 0) {
            float m = wred2[0];
#pragma unroll
            for (int k = 1; k < 8; k++) m = fmaxf(m, wred2[k]);
            atomicMax(&g_maxLp, __float_as_uint(m));
        }
    }
}

// ---------------- launch ----------------
extern "C" void kernel_launch(void* const* d_in, const int* in_sizes, int n_in,
                              void* d_out, int out_size) {
    const float* L = nullptr;
    const float* W = nullptr;
    for (int i = 0; i < n_in; i++) {
        if (in_sizes[i] == BATCH * VOCAB)     L = (const float*)d_in[i];
        else if (in_sizes[i] == VOCAB * RANK) W = (const float*)d_in[i];
    }
    if (!L && n_in >= 2) L = (const float*)d_in[1];
    if (!W && n_in >= 3) W = (const float*)d_in[2];
    float* out = (float*)d_out;

    cudaFuncSetAttribute(k_gemm1, cudaFuncAttributeMaxDynamicSharedMemorySize,
                         G1_TOTAL);
    cudaFuncSetAttribute(k_pass<false>, cudaFuncAttributeMaxDynamicSharedMemorySize,
                         SM2_TOTAL);
    cudaFuncSetAttribute(k_pass<true>, cudaFuncAttributeMaxDynamicSharedMemorySize,
                         SM2_TOTAL);

    k_init<<<(BATCH * RANK) / 256, 256>>>();
    k_gemm1<<<dim3(NKC1, 2), 256, G1_TOTAL>>>(L, W);
    k_red<<<dim3((BATCH * RANK) / 256, KGRP), 256>>>();
    k_pass<false><<<dim3(VOCAB / 128, BATCH / 128), 256, SM2_TOTAL>>>(L, W, out);
    k_pass<true ><<<dim3(VOCAB / 128, BATCH / 128), 256, SM2_TOTAL>>>(L, W, out);
}